// round 10
// baseline (speedup 1.0000x reference)
#include <cuda_runtime.h>

// Problem constants (fixed by setup_inputs)
#define BS      64
#define C_TS    128
#define C_CTS   256
#define T_LEN   2048
#define N_CAT   32
#define N_CONT  64

#define MASK_P    0.15f
#define REPLACE_P 0.80f
#define RAND_HI   0.90f   // REPLACE_P + RANDOM_P

// Decision codes (int32): -2 keep, -1 zero, >=0 swap index within row
#define CODE_KEEP  (-2)
#define CODE_ZERO  (-1)

// Scratch: per-(b,t) decision codes (512 KB each, L2-resident)
__device__ int g_code_ts [BS * T_LEN];
__device__ int g_code_cts[BS * T_LEN];

// ---------------------------------------------------------------------------
// Precompute kernel: encodes decisions for both TS tensors (R2-verbatim,
// static tail removed).
// ---------------------------------------------------------------------------
#define DEC_N      (BS * T_LEN)          // 131072 per tensor
#define DEC_THREADS 256
#define DEC_PER_T   4
#define DEC_BLOCKS  ((2 * DEC_N) / (DEC_THREADS * DEC_PER_T))   // 256

__device__ __forceinline__ int decide(float um, float ua, int ridx)
{
    if (um < MASK_P) {
        if (ua < REPLACE_P) return CODE_ZERO;
        if (ua < RAND_HI)   return ridx;
    }
    return CODE_KEEP;
}

__global__ void precompute_kernel(const float* __restrict__ u_ts_mask,
                                  const float* __restrict__ u_ts_act,
                                  const int*   __restrict__ r_ts_idx,
                                  const float* __restrict__ u_cts_mask,
                                  const float* __restrict__ u_cts_act,
                                  const int*   __restrict__ r_cts_idx)
{
    int blk = blockIdx.x;
    int tid = threadIdx.x;

    long base = ((long)blk * DEC_THREADS + tid) * DEC_PER_T;
    const float* um;
    const float* ua;
    const int*   ri;
    int* code;
    long off;
    if (base < DEC_N) { um = u_ts_mask;  ua = u_ts_act;  ri = r_ts_idx;  code = g_code_ts;  off = base; }
    else              { um = u_cts_mask; ua = u_cts_act; ri = r_cts_idx; code = g_code_cts; off = base - DEC_N; }

    float4 m4 = *(const float4*)(um + off);
    float4 a4 = *(const float4*)(ua + off);
    int4   r4 = *(const int4*)  (ri + off);

    int4 c4;
    c4.x = decide(m4.x, a4.x, r4.x);
    c4.y = decide(m4.y, a4.y, r4.y);
    c4.z = decide(m4.z, a4.z, r4.z);
    c4.w = decide(m4.w, a4.w, r4.w);
    *(int4*)(code + off) = c4;
}

// ---------------------------------------------------------------------------
// Static cat + cont kernel. Single block, parallel mean reduction.
// ---------------------------------------------------------------------------
__global__ void static_kernel(const int*   __restrict__ x_cat,
                              const float* __restrict__ x_cont,
                              const float* __restrict__ u_cat_mask,
                              const float* __restrict__ u_cat_act,
                              const int*   __restrict__ r_cat_val,
                              const float* __restrict__ u_cont_mask,
                              const float* __restrict__ u_cont_act,
                              const int*   __restrict__ r_cont_idx,
                              float* __restrict__ out_cat,
                              float* __restrict__ out_cont)
{
    int tid = threadIdx.x;
    __shared__ float partial[4][N_CONT];
    __shared__ float means[N_CONT];

    {
        int j = tid & (N_CONT - 1);        // column
        int chunk = tid >> 6;              // 0..3, 16 rows each
        float s = 0.0f;
        for (int b = chunk * 16; b < chunk * 16 + 16; b++)
            s += x_cont[b * N_CONT + j];
        partial[chunk][j] = s;
    }
    __syncthreads();
    if (tid < N_CONT) {
        means[tid] = (partial[0][tid] + partial[1][tid] +
                      partial[2][tid] + partial[3][tid]) * (1.0f / BS);
    }
    __syncthreads();

    // categorical: BS*N_CAT = 2048 elements
    for (int i = tid; i < BS * N_CAT; i += blockDim.x) {
        float um = u_cat_mask[i];
        float ua = u_cat_act[i];
        int v = x_cat[i];
        if (um < MASK_P) {
            if (ua < REPLACE_P)    v = 0;
            else if (ua < RAND_HI) v = r_cat_val[i];
        }
        out_cat[i] = (float)v;
    }

    // continuous: BS*N_CONT = 4096 elements
    for (int i = tid; i < BS * N_CONT; i += blockDim.x) {
        int j = i & (N_CONT - 1);
        float um = u_cont_mask[i];
        float ua = u_cont_act[i];
        float v = x_cont[i];
        if (um < MASK_P) {
            if (ua < REPLACE_P)    v = means[j];
            else if (ua < RAND_HI) v = x_cont[r_cont_idx[i] * N_CONT + j];
        }
        out_cont[i] = v;
    }
}

// ---------------------------------------------------------------------------
// Fused streaming kernel: R2-VERBATIM. TS blocks then CTS blocks in one grid.
// Thread = 4 consecutive t. Loads: code int4 (L2-hit) + x float4. Store float4.
// ---------------------------------------------------------------------------
#define TS_GROUPS   ((long)BS * C_TS  * T_LEN / 4)   // 4,194,304
#define CTS_GROUPS  ((long)BS * C_CTS * T_LEN / 4)   // 8,388,608
#define MAIN_THREADS 256
#define TS_BLOCKS   (TS_GROUPS  / MAIN_THREADS)      // 16384
#define CTS_BLOCKS  (CTS_GROUPS / MAIN_THREADS)      // 32768

__global__ void __launch_bounds__(MAIN_THREADS)
fused_mask_kernel(const float* __restrict__ x_ts,
                  float* __restrict__ out_ts,
                  const float* __restrict__ x_cts,
                  float* __restrict__ out_cts)
{
    long blk = blockIdx.x;
    const float* x;
    float* out;
    const int* code;
    int C;
    if (blk < TS_BLOCKS) {
        x = x_ts; out = out_ts; code = g_code_ts; C = C_TS;
    } else {
        blk -= TS_BLOCKS;
        x = x_cts; out = out_cts; code = g_code_cts; C = C_CTS;
    }

    long gid = blk * MAIN_THREADS + threadIdx.x;
    const int groups_per_row = T_LEN / 4;
    int  t0 = (int)(gid % groups_per_row) * 4;
    long bc = gid / groups_per_row;          // b*C + c
    int  b  = (int)(bc / C);

    const int4   c4 = *(const int4*)(code + (long)b * T_LEN + t0);
    const float* row = x + bc * T_LEN;
    float4 x4 = *(const float4*)(row + t0);

    float xv[4] = {x4.x, x4.y, x4.z, x4.w};
    int   cv[4] = {c4.x, c4.y, c4.z, c4.w};

    float o[4];
#pragma unroll
    for (int i = 0; i < 4; i++) {
        float v = xv[i];
        int c = cv[i];
        if (c != CODE_KEEP) {
            v = (c >= 0) ? __ldg(row + c) : 0.0f;
        }
        o[i] = v;
    }

    *(float4*)(out + bc * T_LEN + t0) = make_float4(o[0], o[1], o[2], o[3]);
}

// ---------------------------------------------------------------------------
// Launch
// ---------------------------------------------------------------------------
extern "C" void kernel_launch(void* const* d_in, const int* in_sizes, int n_in,
                              void* d_out, int out_size)
{
    const float* x_ts     = (const float*)d_in[0];
    const float* x_ts_cat = (const float*)d_in[1];
    const int*   x_cat    = (const int*)  d_in[2];
    const float* x_cont   = (const float*)d_in[3];

    const float* u_ts_mask  = (const float*)d_in[4];
    const float* u_ts_act   = (const float*)d_in[5];
    const int*   r_ts_idx   = (const int*)  d_in[6];
    const float* u_cts_mask = (const float*)d_in[7];
    const float* u_cts_act  = (const float*)d_in[8];
    const int*   r_cts_idx  = (const int*)  d_in[9];

    const float* u_cat_mask = (const float*)d_in[10];
    const float* u_cat_act  = (const float*)d_in[11];
    const int*   r_cat_val  = (const int*)  d_in[12];
    const float* u_cont_mask= (const float*)d_in[13];
    const float* u_cont_act = (const float*)d_in[14];
    const int*   r_cont_idx = (const int*)  d_in[15];

    float* out = (float*)d_out;
    const long TS_ELEMS  = (long)BS * C_TS  * T_LEN;   // 16,777,216
    const long CTS_ELEMS = (long)BS * C_CTS * T_LEN;   // 33,554,432
    float* out_ts   = out;
    float* out_cts  = out + TS_ELEMS;
    float* out_cat  = out + TS_ELEMS + CTS_ELEMS;
    float* out_cont = out_cat + (long)BS * N_CAT;

    precompute_kernel<<<DEC_BLOCKS, DEC_THREADS>>>(
        u_ts_mask, u_ts_act, r_ts_idx,
        u_cts_mask, u_cts_act, r_cts_idx);

    static_kernel<<<1, 256>>>(x_cat, x_cont,
                              u_cat_mask, u_cat_act, r_cat_val,
                              u_cont_mask, u_cont_act, r_cont_idx,
                              out_cat, out_cont);

    fused_mask_kernel<<<(int)(TS_BLOCKS + CTS_BLOCKS), MAIN_THREADS>>>(
        x_ts, out_ts, x_ts_cat, out_cts);
}